// round 12
// baseline (speedup 1.0000x reference)
#include <cuda_runtime.h>
#include <cuda_fp16.h>

// ---------------------------------------------------------------------------
// EnhancedQuanvolution via warp-level HMMA, fp16 A, fp16 hi/lo W (2 products).
// R12: + L2 prefetch of chunk c+1 and a rolling 3-deep LDG window in the
// feature loop (MLP 2 -> ~6) to push DRAM utilization toward the stream
// floor. Otherwise identical to R11. block=448 (14 warps), grid=147.
// ---------------------------------------------------------------------------

static constexpr int THREADS   = 448;
static constexpr int IMG_BLK   = 448;
static constexpr int NCHUNK    = 14;
static constexpr int FROW      = 144;              // 64 k * 2B + 16B pad
static constexpr int FBUF      = 32 * FROW;        // 4608 B per warp
static constexpr int WCHUNK    = 2 * 16 * FROW;    // 4608 B per chunk (Whi+Wlo)
static constexpr int OFF_FEAT  = NCHUNK * WCHUNK;  // 64512
static constexpr int OFF_BIAS  = OFF_FEAT + 14 * FBUF;  // 129024
static constexpr int SMEM_REQ  = OFF_BIAS + 64;

__device__ __align__(16) unsigned char gWp[NCHUNK * WCHUNK];

__global__ void prep_w(const float* __restrict__ W) {
    int i = blockIdx.x * blockDim.x + threadIdx.x;   // 14*16*64 = 14336
    if (i >= NCHUNK * 16 * 64) return;
    int c = i >> 10, n = (i >> 6) & 15, k = i & 63;
    float w = (n < 10 && k < 56) ? W[n * 784 + c * 56 + k] : 0.f;
    __half h = __float2half_rn(w);
    __half l = __float2half_rn(w - __half2float(h));
    unsigned char* base = gWp + c * WCHUNK;
    *(__half*)(base + n * FROW + k * 2) = h;
    *(__half*)(base + 16 * FROW + n * FROW + k * 2) = l;
}

__device__ __forceinline__ void cp_async16(unsigned dst, const void* src) {
    asm volatile("cp.async.cg.shared.global [%0], [%1], 16;" :: "r"(dst), "l"(src) : "memory");
}
__device__ __forceinline__ unsigned lds32(unsigned a) {
    unsigned v; asm volatile("ld.shared.b32 %0, [%1];" : "=r"(v) : "r"(a)); return v;
}
__device__ __forceinline__ void sts128(unsigned a, unsigned r0, unsigned r1,
                                       unsigned r2, unsigned r3) {
    asm volatile("st.shared.v4.b32 [%0], {%1,%2,%3,%4};"
                 :: "r"(a), "r"(r0), "r"(r1), "r"(r2), "r"(r3) : "memory");
}
__device__ __forceinline__ void ldsm4(unsigned* r, unsigned a) {
    asm volatile("ldmatrix.sync.aligned.m8n8.x4.shared.b16 {%0,%1,%2,%3}, [%4];"
                 : "=r"(r[0]), "=r"(r[1]), "=r"(r[2]), "=r"(r[3]) : "r"(a));
}
__device__ __forceinline__ void mma16816(float* d, const unsigned* a,
                                         unsigned b0, unsigned b1) {
    asm volatile("mma.sync.aligned.m16n8k16.row.col.f32.f16.f16.f32 "
                 "{%0,%1,%2,%3}, {%4,%5,%6,%7}, {%8,%9}, {%0,%1,%2,%3};"
                 : "+f"(d[0]), "+f"(d[1]), "+f"(d[2]), "+f"(d[3])
                 : "r"(a[0]), "r"(a[1]), "r"(a[2]), "r"(a[3]), "r"(b0), "r"(b1));
}
__device__ __forceinline__ unsigned pack_h2(float a, float b) {
    unsigned r;
    asm("cvt.rn.f16x2.f32 %0, %1, %2;" : "=r"(r) : "f"(b), "f"(a));
    return r;
}
__device__ __forceinline__ void pf_l2(const void* p) {
    asm volatile("prefetch.global.L2 [%0];" :: "l"(p));
}

__global__ __launch_bounds__(THREADS, 1)
void quanv_hmma(const float* __restrict__ x, const float* __restrict__ bias,
                float* __restrict__ out, int batch) {
    extern __shared__ unsigned char sm[];
    const unsigned smb = (unsigned)__cvta_generic_to_shared(sm);
    float* bias_sh = (float*)(sm + OFF_BIAS);

    const int tid = threadIdx.x, lane = tid & 31, wid = tid >> 5;

    // ---- init: copy pre-split W, zero feat buffers, bias ---------------------
#pragma unroll
    for (int r = 0; r < 9; r++) {
        int off = (tid + r * THREADS) * 16;
        cp_async16(smb + off, gWp + off);
    }
    asm volatile("cp.async.commit_group;" ::: "memory");
    float4 z4 = make_float4(0.f, 0.f, 0.f, 0.f);
#pragma unroll
    for (int r = 0; r < 9; r++) {
        int off = OFF_FEAT + (tid + r * THREADS) * 16;
        *(float4*)(sm + off) = z4;
    }
    if (tid < 10) bias_sh[tid] = bias[tid];
    asm volatile("cp.async.wait_group 0;" ::: "memory");
    __syncthreads();

    const int wimg = blockIdx.x * IMG_BLK + wid * 32;
    const unsigned fbuf = smb + OFF_FEAT + wid * FBUF;

    // clamped prefetch image for this lane
    int pimg = wimg + lane;
    if (pimg >= batch) pimg = batch - 1;
    const char* pfb = (const char*)(x + (size_t)pimg * 784);

    float d[2][2][4];
#pragma unroll
    for (int m = 0; m < 2; m++)
#pragma unroll
        for (int nt = 0; nt < 2; nt++)
#pragma unroll
            for (int e = 0; e < 4; e++) d[m][nt][e] = 0.f;

    // prefetch chunk 0
    pf_l2(pfb); pf_l2(pfb + 96); pf_l2(pfb + 208);

#pragma unroll 1
    for (int c = 0; c < NCHUNK; c++) {
        __syncwarp();
        // ---- L2 prefetch for chunk c+1 (fire-and-forget) ---------------------
        if (c + 1 < NCHUNK) {
            const char* pp = pfb + (c + 1) * 224;
            pf_l2(pp); pf_l2(pp + 96); pf_l2(pp + 208);
        }

        // ---- feats: rolling 3-deep LDG window --------------------------------
        auto ld_t = [&](int t, float4& q0, float4& q1) {
            int n = lane + 32 * t;
            int img = n / 7, j = n - img * 7;
            q0 = z4; q1 = z4;
            if (wimg + img < batch) {
                const float* px = x + (size_t)(wimg + img) * 784 + c * 56 + j * 4;
                q0 = *(const float4*)px;          // row 2c
                q1 = *(const float4*)(px + 28);   // row 2c+1
            }
        };
        auto do_t = [&](int t, float4 q0, float4 q1) {
            float f0 = __cosf(q0.x), f1 = f0 * __cosf(q0.y);
            float f2 = f1 * __cosf(q1.x), f3 = f2 * __cosf(q1.y);
            float g0 = __cosf(q0.z), g1 = g0 * __cosf(q0.w);
            float g2 = g1 * __cosf(q1.z), g3 = g2 * __cosf(q1.w);
            int n = lane + 32 * t;
            int img = n / 7, j = n - img * 7;
            unsigned sa = fbuf + img * FROW + j * 16;
            sts128(sa, pack_h2(f0, f1), pack_h2(f2, f3),
                       pack_h2(g0, g1), pack_h2(g2, g3));
        };
        {
            float4 a0, a1, b0, b1, e0, e1;
            ld_t(0, a0, a1); ld_t(1, b0, b1); ld_t(2, e0, e1);
            do_t(0, a0, a1); ld_t(3, a0, a1);
            do_t(1, b0, b1); ld_t(4, b0, b1);
            do_t(2, e0, e1); ld_t(5, e0, e1);
            do_t(3, a0, a1); ld_t(6, a0, a1);
            do_t(4, b0, b1);
            do_t(5, e0, e1);
            do_t(6, a0, a1);
        }
        __syncwarp();

        // ---- B fragments (hi, lo W tiles) -------------------------------------
        const unsigned wb = smb + c * WCHUNK;
        unsigned bh[2][4][2], bl[2][4][2];
#pragma unroll
        for (int nt = 0; nt < 2; nt++)
#pragma unroll
            for (int T = 0; T < 4; T++) {
                unsigned ba = wb + (nt * 8 + (lane >> 2)) * FROW + T * 32 + (lane & 3) * 4;
                bh[nt][T][0] = lds32(ba);
                bh[nt][T][1] = lds32(ba + 16);
                bl[nt][T][0] = lds32(ba + 16 * FROW);
                bl[nt][T][1] = lds32(ba + 16 * FROW + 16);
            }

        // ---- A fragments + MMA -------------------------------------------------
        const unsigned rowsel = (lane & 7) + 8 * ((lane >> 3) & 1);
        const unsigned koff = ((lane >> 4) & 1) * 16;
#pragma unroll
        for (int m = 0; m < 2; m++) {
            unsigned ah[4][4];
#pragma unroll
            for (int T = 0; T < 4; T++)
                ldsm4(ah[T], fbuf + (16 * m + rowsel) * FROW + T * 32 + koff);
#pragma unroll
            for (int nt = 0; nt < 2; nt++)
#pragma unroll
                for (int T = 0; T < 4; T++) {
                    mma16816(d[m][nt], ah[T], bh[nt][T][0], bh[nt][T][1]);
                    mma16816(d[m][nt], ah[T], bl[nt][T][0], bl[nt][T][1]);
                }
        }
    }

    // ---- epilogue: bias + log_softmax (4-lane groups per image) ---------------
    const int q = lane & 3;
    const float b0 = bias_sh[2 * q], b1 = bias_sh[2 * q + 1];
    const float b8 = bias_sh[8], b9 = bias_sh[9];
#pragma unroll
    for (int m = 0; m < 2; m++)
#pragma unroll
        for (int h = 0; h < 2; h++) {
            int img = wimg + 16 * m + 8 * h + (lane >> 2);
            float v0 = d[m][0][2 * h] + b0;
            float v1 = d[m][0][2 * h + 1] + b1;
            float v2 = (q == 0) ? d[m][1][2 * h] + b8 : -1e30f;
            float v3 = (q == 0) ? d[m][1][2 * h + 1] + b9 : -1e30f;
            float mx = fmaxf(fmaxf(v0, v1), fmaxf(v2, v3));
            mx = fmaxf(mx, __shfl_xor_sync(0xffffffffu, mx, 1));
            mx = fmaxf(mx, __shfl_xor_sync(0xffffffffu, mx, 2));
            float s = __expf(v0 - mx) + __expf(v1 - mx);
            if (q == 0) s += __expf(v2 - mx) + __expf(v3 - mx);
            s += __shfl_xor_sync(0xffffffffu, s, 1);
            s += __shfl_xor_sync(0xffffffffu, s, 2);
            float lse = mx + __logf(s);
            if (img < batch) {
                float* op = out + (size_t)img * 10;
                *(float2*)(op + 2 * q) = make_float2(v0 - lse, v1 - lse);
                if (q == 0) *(float2*)(op + 8) = make_float2(v2 - lse, v3 - lse);
            }
        }
}

extern "C" void kernel_launch(void* const* d_in, const int* in_sizes, int n_in,
                              void* d_out, int out_size) {
    const float* x = (const float*)d_in[0];   // (B,1,28,28) fp32
    const float* W = (const float*)d_in[1];   // (10,784)    fp32
    const float* b = (const float*)d_in[2];   // (10,)       fp32
    float* out = (float*)d_out;               // (B,10)      fp32

    int batch = in_sizes[0] / 784;

    prep_w<<<(NCHUNK * 16 * 64 + 255) / 256, 256>>>(W);

    int grid = (batch + IMG_BLK - 1) / IMG_BLK;
    cudaFuncSetAttribute(quanv_hmma, cudaFuncAttributeMaxDynamicSharedMemorySize, SMEM_REQ);
    quanv_hmma<<<grid, THREADS, SMEM_REQ>>>(x, b, out, batch);
}